// round 1
// baseline (speedup 1.0000x reference)
#include <cuda_runtime.h>

#define BB 4
#define NN 512
#define MM 512
#define LD 512
#define AG 256
#define ROWS (BB * NN)   // 2048

// Scratch for projected activations (allocation-free rule: device globals).
__device__ float g_dl[ROWS * AG];   // [row][a], row = b*N + n
__device__ float g_cl[ROWS * AG];   // [row][a], row = b*M + m

__device__ __forceinline__ float fast_tanh(float x) {
    float y;
    asm("tanh.approx.f32 %0, %1;" : "=f"(y) : "f"(x));
    return y;
}

// ---------------------------------------------------------------------------
// Projection GEMM: out[row][a] = sum_k in[row][k] * W[k][a] + bias[a]
// Both projections in ONE launch: blocks 0..63 -> dl, 64..127 -> cl.
// BM=64, BN=128, BK=16, 256 threads, per-thread 4x8 register tile.
// ---------------------------------------------------------------------------
__global__ __launch_bounds__(256) void proj_kernel(
    const float* __restrict__ data, const float* __restrict__ crit,
    const float* __restrict__ Wl, const float* __restrict__ bl,
    const float* __restrict__ Wr, const float* __restrict__ br)
{
    __shared__ float As[16][64];    // [k][m]
    __shared__ float Bs[16][128];   // [k][n]

    int bid = blockIdx.x;
    const float* A; const float* W; const float* bias; float* out;
    if (bid < 64) { A = data; W = Wl; bias = bl; out = g_dl; }
    else          { A = crit; W = Wr; bias = br; out = g_cl; bid -= 64; }
    const int row0 = (bid >> 1) * 64;
    const int col0 = (bid & 1) * 128;

    const int tid = threadIdx.x;
    const int ar  = tid >> 2;            // 0..63  (A row within tile)
    const int ac  = (tid & 3) << 2;      // 0,4,8,12 (A col group)
    const int ty  = tid >> 4;            // 0..15  -> rows ty*4
    const int tx  = tid & 15;            // 0..15  -> cols tx*8
    const int brow = tid >> 5;           // 0..7
    const int bcol = (tid & 31) << 2;    // 0..124

    float acc[4][8];
#pragma unroll
    for (int i = 0; i < 4; i++)
#pragma unroll
        for (int j = 0; j < 8; j++) acc[i][j] = 0.f;

    for (int k0 = 0; k0 < LD; k0 += 16) {
        float4 av  = *(const float4*)(A + (row0 + ar) * LD + k0 + ac);
        float4 bv0 = *(const float4*)(W + (k0 + brow) * AG + col0 + bcol);
        float4 bv1 = *(const float4*)(W + (k0 + 8 + brow) * AG + col0 + bcol);

        As[ac + 0][ar] = av.x;
        As[ac + 1][ar] = av.y;
        As[ac + 2][ar] = av.z;
        As[ac + 3][ar] = av.w;
        *(float4*)&Bs[brow][bcol]     = bv0;
        *(float4*)&Bs[brow + 8][bcol] = bv1;
        __syncthreads();

#pragma unroll
        for (int k = 0; k < 16; k++) {
            float a[4], b[8];
            *(float4*)a       = *(const float4*)&As[k][ty << 2];
            *(float4*)(b)     = *(const float4*)&Bs[k][tx << 3];
            *(float4*)(b + 4) = *(const float4*)&Bs[k][(tx << 3) + 4];
#pragma unroll
            for (int i = 0; i < 4; i++)
#pragma unroll
                for (int j = 0; j < 8; j++)
                    acc[i][j] = fmaf(a[i], b[j], acc[i][j]);
        }
        __syncthreads();
    }

#pragma unroll
    for (int i = 0; i < 4; i++) {
        int row = row0 + (ty << 2) + i;
#pragma unroll
        for (int j4 = 0; j4 < 2; j4++) {
            int c = col0 + (tx << 3) + (j4 << 2);
            float4 v;
            v.x = acc[i][(j4 << 2) + 0] + bias[c + 0];
            v.y = acc[i][(j4 << 2) + 1] + bias[c + 1];
            v.z = acc[i][(j4 << 2) + 2] + bias[c + 2];
            v.w = acc[i][(j4 << 2) + 3] + bias[c + 3];
            *(float4*)(out + row * AG + c) = v;
        }
    }
}

// ---------------------------------------------------------------------------
// Distance kernel: dists[b,n,m] = sum_a tanh(dl[b,n,a] + cl[b,m,a]) * agg[a]
// 64x64 output tile per block, 256 threads, 4x4 register tile per thread.
// dl/cl staged a-major in smem (stride 65 pad -> conflict-free transpose STS).
// ---------------------------------------------------------------------------
__global__ __launch_bounds__(256) void dist_kernel(
    const float* __restrict__ agg, float* __restrict__ out)
{
    __shared__ float dls[32][65];
    __shared__ float cls[32][65];
    __shared__ float aggs[256];

    const int b  = blockIdx.z;
    const int n0 = blockIdx.x << 6;
    const int m0 = blockIdx.y << 6;
    const int tid = threadIdx.x;
    const int ty  = tid >> 4;   // 0..15 -> n rows ty*4
    const int tx  = tid & 15;   // 0..15 -> m cols tx*4

    aggs[tid] = agg[tid];

    const float* dlb = g_dl + (b * NN + n0) * AG;
    const float* clb = g_cl + (b * MM + m0) * AG;

    float acc[4][4];
#pragma unroll
    for (int i = 0; i < 4; i++)
#pragma unroll
        for (int j = 0; j < 4; j++) acc[i][j] = 0.f;

    for (int a0 = 0; a0 < AG; a0 += 32) {
        __syncthreads();   // protect previous chunk reads (covers aggs on iter 0)
#pragma unroll
        for (int h = 0; h < 2; h++) {
            int idx = tid + (h << 8);       // 0..511
            int r   = idx >> 3;             // 0..63
            int a4  = (idx & 7) << 2;       // 0,4,...,28
            float4 v = *(const float4*)(dlb + r * AG + a0 + a4);
            dls[a4 + 0][r] = v.x;
            dls[a4 + 1][r] = v.y;
            dls[a4 + 2][r] = v.z;
            dls[a4 + 3][r] = v.w;
            float4 w = *(const float4*)(clb + r * AG + a0 + a4);
            cls[a4 + 0][r] = w.x;
            cls[a4 + 1][r] = w.y;
            cls[a4 + 2][r] = w.z;
            cls[a4 + 3][r] = w.w;
        }
        __syncthreads();

#pragma unroll 4
        for (int a = 0; a < 32; a++) {
            float d[4], c[4];
#pragma unroll
            for (int i = 0; i < 4; i++) d[i] = dls[a][(ty << 2) + i];
#pragma unroll
            for (int j = 0; j < 4; j++) c[j] = cls[a][(tx << 2) + j];
            float ag = aggs[a0 + a];
#pragma unroll
            for (int i = 0; i < 4; i++)
#pragma unroll
                for (int j = 0; j < 4; j++)
                    acc[i][j] = fmaf(fast_tanh(d[i] + c[j]), ag, acc[i][j]);
        }
    }

#pragma unroll
    for (int i = 0; i < 4; i++) {
        int n = n0 + (ty << 2) + i;
        float4 v = make_float4(acc[i][0], acc[i][1], acc[i][2], acc[i][3]);
        *(float4*)(out + ((size_t)(b * NN + n) << 9) + m0 + (tx << 2)) = v;
    }
}

extern "C" void kernel_launch(void* const* d_in, const int* in_sizes, int n_in,
                              void* d_out, int out_size) {
    const float* data = (const float*)d_in[0];
    const float* crit = (const float*)d_in[1];
    const float* Wl   = (const float*)d_in[2];
    const float* bl   = (const float*)d_in[3];
    const float* Wr   = (const float*)d_in[4];
    const float* br   = (const float*)d_in[5];
    const float* agg  = (const float*)d_in[6];
    float* out = (float*)d_out;

    proj_kernel<<<128, 256>>>(data, crit, Wl, bl, Wr, br);
    dist_kernel<<<dim3(8, 8, 4), 256>>>(agg, out);
}

// round 2
// speedup vs baseline: 1.2143x; 1.2143x over previous
#include <cuda_runtime.h>

#define BB 4
#define NN 512
#define MM 512
#define LD 512
#define AG 256
#define ROWS (BB * NN)   // 2048

__device__ float g_dl[ROWS * AG];   // [row][a]
__device__ float g_cl[ROWS * AG];   // [row][a]

__device__ __forceinline__ float fast_tanh(float x) {
    float y;
    asm("tanh.approx.f32 %0, %1;" : "=f"(y) : "f"(x));
    return y;
}

// ---------------------------------------------------------------------------
// Projection GEMM: out[row][a] = sum_k in[row][k] * W[k][a] + bias[a]
// BM=64, BN=64, BK=16, 256 threads, 4x4/thread, double-buffered smem.
// grid (32 row-tiles, 4 col-tiles, 2 gemms) = 256 blocks.
// ---------------------------------------------------------------------------
__global__ __launch_bounds__(256) void proj_kernel(
    const float* __restrict__ data, const float* __restrict__ crit,
    const float* __restrict__ Wl, const float* __restrict__ bl,
    const float* __restrict__ Wr, const float* __restrict__ br)
{
    __shared__ float As[2][16][68];   // [buf][k][m], pad 68 (16B-aligned rows)
    __shared__ float Bs[2][16][68];   // [buf][k][n]

    const float* A; const float* W; const float* bias; float* out;
    if (blockIdx.z == 0) { A = data; W = Wl; bias = bl; out = g_dl; }
    else                 { A = crit; W = Wr; bias = br; out = g_cl; }
    const int row0 = blockIdx.x * 64;
    const int col0 = blockIdx.y * 64;

    const int tid = threadIdx.x;
    const int ar  = tid >> 2;            // 0..63
    const int ac  = (tid & 3) << 2;      // 0,4,8,12
    const int bro = tid >> 4;            // 0..15
    const int bco = (tid & 15) << 2;     // 0..60
    const int ty  = tid >> 4;            // 0..15 -> rows 4ty
    const int tx  = tid & 15;            // 0..15 -> cols 4tx

    const float* Aptr = A + (row0 + ar) * LD + ac;
    const float* Wptr = W + bro * AG + col0 + bco;

    float acc[4][4];
#pragma unroll
    for (int i = 0; i < 4; i++)
#pragma unroll
        for (int j = 0; j < 4; j++) acc[i][j] = 0.f;

    // prologue: chunk 0 -> buf 0
    {
        float4 av = *(const float4*)(Aptr);
        float4 bv = *(const float4*)(Wptr);
        As[0][ac + 0][ar] = av.x;
        As[0][ac + 1][ar] = av.y;
        As[0][ac + 2][ar] = av.z;
        As[0][ac + 3][ar] = av.w;
        *(float4*)&Bs[0][bro][bco] = bv;
    }
    __syncthreads();

    int cur = 0;
    for (int k0 = 0; k0 < LD; k0 += 16) {
        float4 an, bn;
        const bool more = (k0 + 16) < LD;
        if (more) {
            an = *(const float4*)(Aptr + k0 + 16);
            bn = *(const float4*)(Wptr + (size_t)(k0 + 16) * AG);
        }
#pragma unroll
        for (int k = 0; k < 16; k++) {
            float a[4], b[4];
            *(float4*)a = *(const float4*)&As[cur][k][ty << 2];
            *(float4*)b = *(const float4*)&Bs[cur][k][tx << 2];
#pragma unroll
            for (int i = 0; i < 4; i++)
#pragma unroll
                for (int j = 0; j < 4; j++)
                    acc[i][j] = fmaf(a[i], b[j], acc[i][j]);
        }
        if (more) {
            int nxt = cur ^ 1;
            As[nxt][ac + 0][ar] = an.x;
            As[nxt][ac + 1][ar] = an.y;
            As[nxt][ac + 2][ar] = an.z;
            As[nxt][ac + 3][ar] = an.w;
            *(float4*)&Bs[nxt][bro][bco] = bn;
            __syncthreads();
            cur = nxt;
        }
    }

#pragma unroll
    for (int i = 0; i < 4; i++) {
        int row = row0 + (ty << 2) + i;
        int c   = col0 + (tx << 2);
        float4 v;
        v.x = acc[i][0] + bias[c + 0];
        v.y = acc[i][1] + bias[c + 1];
        v.z = acc[i][2] + bias[c + 2];
        v.w = acc[i][3] + bias[c + 3];
        *(float4*)(out + row * AG + c) = v;
    }
}

// ---------------------------------------------------------------------------
// Distance kernel: dists[b,n,m] = sum_a tanh(dl[b,n,a] + cl[b,m,a]) * agg[a]
// 32x32 tile / block (grid 1024 -> 98.8% wave balance), 256 threads, 2x2/thread.
// a staged in chunks of 64, a-major smem, stride 34 (even -> float2 reads).
// ---------------------------------------------------------------------------
__global__ __launch_bounds__(256) void dist_kernel(
    const float* __restrict__ agg, float* __restrict__ out)
{
    __shared__ float dls[64][34];
    __shared__ float cls[64][34];
    __shared__ float aggs[AG];

    const int b  = blockIdx.z;
    const int n0 = blockIdx.x << 5;
    const int m0 = blockIdx.y << 5;
    const int tid = threadIdx.x;
    const int ty2 = (tid >> 4) << 1;   // n rows ty2, ty2+1
    const int tx2 = (tid & 15) << 1;   // m cols tx2, tx2+1

    aggs[tid] = agg[tid];

    const float* dlb = g_dl + (size_t)(b * NN + n0) * AG;
    const float* clb = g_cl + (size_t)(b * MM + m0) * AG;

    float a00 = 0.f, a01 = 0.f, a10 = 0.f, a11 = 0.f;

    for (int a0 = 0; a0 < AG; a0 += 64) {
        __syncthreads();   // protect previous chunk reads (covers aggs on iter 0)
#pragma unroll
        for (int h = 0; h < 2; h++) {
            int idx = tid + (h << 8);       // 0..511
            int r   = idx >> 4;             // 0..31
            int a4  = (idx & 15) << 2;      // 0..60
            float4 v = *(const float4*)(dlb + r * AG + a0 + a4);
            dls[a4 + 0][r] = v.x;
            dls[a4 + 1][r] = v.y;
            dls[a4 + 2][r] = v.z;
            dls[a4 + 3][r] = v.w;
            float4 w = *(const float4*)(clb + r * AG + a0 + a4);
            cls[a4 + 0][r] = w.x;
            cls[a4 + 1][r] = w.y;
            cls[a4 + 2][r] = w.z;
            cls[a4 + 3][r] = w.w;
        }
        __syncthreads();

#pragma unroll 4
        for (int a = 0; a < 64; a++) {
            float2 d = *(const float2*)&dls[a][ty2];
            float2 c = *(const float2*)&cls[a][tx2];
            float g = aggs[a0 + a];
            a00 = fmaf(fast_tanh(d.x + c.x), g, a00);
            a01 = fmaf(fast_tanh(d.x + c.y), g, a01);
            a10 = fmaf(fast_tanh(d.y + c.x), g, a10);
            a11 = fmaf(fast_tanh(d.y + c.y), g, a11);
        }
    }

    float* o0 = out + ((size_t)(b * NN + n0 + ty2) << 9) + m0 + tx2;
    float* o1 = o0 + MM;
    *(float2*)o0 = make_float2(a00, a01);
    *(float2*)o1 = make_float2(a10, a11);
}

extern "C" void kernel_launch(void* const* d_in, const int* in_sizes, int n_in,
                              void* d_out, int out_size) {
    const float* data = (const float*)d_in[0];
    const float* crit = (const float*)d_in[1];
    const float* Wl   = (const float*)d_in[2];
    const float* bl   = (const float*)d_in[3];
    const float* Wr   = (const float*)d_in[4];
    const float* br   = (const float*)d_in[5];
    const float* agg  = (const float*)d_in[6];
    float* out = (float*)d_out;

    proj_kernel<<<dim3(32, 4, 2), 256>>>(data, crit, Wl, bl, Wr, br);
    dist_kernel<<<dim3(16, 16, 4), 256>>>(agg, out);
}